// round 17
// baseline (speedup 1.0000x reference)
#include <cuda_runtime.h>
#include <cstdint>

#define NCOLS 2048
#define SROW  2052           // padded smem row stride (floats): 4-bank shift/row
#define ORDER 8
#define NB    148
#define TPB   512
#define TILE  8
#define NT    7

typedef unsigned long long ull;

__device__ __forceinline__ ull pack2(float lo, float hi) {
    ull r; asm("mov.b64 %0, {%1, %2};" : "=l"(r) : "f"(lo), "f"(hi)); return r;
}
__device__ __forceinline__ float2 unpack2(ull v) {
    float2 f; asm("mov.b64 {%0, %1}, %2;" : "=f"(f.x), "=f"(f.y) : "l"(v)); return f;
}
__device__ __forceinline__ ull ffma2(ull a, ull b, ull c) {
    ull d; asm("fma.rn.f32x2 %0, %1, %2, %3;" : "=l"(d) : "l"(a), "l"(b), "l"(c)); return d;
}
__device__ __forceinline__ uint32_t s2u(const void* p) {
    uint32_t a;
    asm("{ .reg .u64 t; cvta.to.shared.u64 t, %1; cvt.u32.u64 %0, t; }"
        : "=r"(a) : "l"(p));
    return a;
}
__device__ __forceinline__ void cp16(uint32_t dst, const float* src) {
    asm volatile("cp.async.cg.shared.global [%0], [%1], 16;" :: "r"(dst), "l"(src));
}
__device__ __forceinline__ void cp_commit() { asm volatile("cp.async.commit_group;"); }
__device__ __forceinline__ void cp_wait0()  { asm volatile("cp.async.wait_group 0;"); }

__device__ __forceinline__ uint32_t cvt_tf32(float f) {
    uint32_t r; asm("cvt.rna.tf32.f32 %0, %1;" : "=r"(r) : "f"(f)); return r;
}
__device__ __forceinline__ void mma_tf32(
    float& c0, float& c1, float& c2, float& c3,
    uint32_t a0, uint32_t a1, uint32_t a2, uint32_t a3,
    uint32_t b0, uint32_t b1)
{
    asm volatile(
        "mma.sync.aligned.m16n8k8.row.col.f32.tf32.tf32.f32 "
        "{%0,%1,%2,%3}, {%4,%5,%6,%7}, {%8,%9}, {%0,%1,%2,%3};"
        : "+f"(c0), "+f"(c1), "+f"(c2), "+f"(c3)
        : "r"(a0), "r"(a1), "r"(a2), "r"(a3), "r"(b0), "r"(b1));
}

// dynamic smem: xbuf[2][TILE][SROW] = 131328 bytes
extern __shared__ float xbuf[];

__global__ void __launch_bounds__(TPB, 1) orth_mma(
    const float* __restrict__ x, const float* __restrict__ v,
    const float* __restrict__ d, const float* __restrict__ bias,
    float* __restrict__ y)
{
    __shared__ float gpart[16 * 36];
    __shared__ float Tneg[64];
    __shared__ float asum[16 * 66];        // [warp][i(8)][row(8)], stride 66
    __shared__ float A2[TILE * 8 * 2];     // duplicated (b,b) per (row,k)

    const int t = threadIdx.x, lane = t & 31, w = t >> 5;
    const int g4 = lane >> 2, q = lane & 3;    // MMA fragment coords
    const int c0 = t * 4;
    const int cbase = w * 128;                 // warp's column chunk

    const int bid = blockIdx.x;
    const int nr = (bid < 52) ? 56 : 55;
    const int r0 = (bid < 52) ? bid * 56 : 52 * 56 + (bid - 52) * 55;

    // ---- kick off prefetch of tile 0 immediately (padded rows) ----
    const uint32_t xb_base = s2u(xbuf);
#pragma unroll
    for (int j = 0; j < TILE; ++j) {
        const int rc = (j < nr) ? j : (nr - 1);
        cp16(xb_base + (uint32_t)(j * SROW + c0) * 4,
             x + (size_t)(r0 + rc) * NCOLS + c0);
    }
    cp_commit();

    // ---- V slice (transient, for Gram + packed V build) ----
    float4 Vf[ORDER];
#pragma unroll
    for (int k = 0; k < ORDER; ++k)
        Vf[k] = *reinterpret_cast<const float4*>(v + k * NCOLS + c0);

    // ================= Prologue: Gram -> Tneg =================
    {
        int idx = 0;
#pragma unroll
        for (int i = 0; i < ORDER; ++i) {
#pragma unroll
            for (int k = i; k < ORDER; ++k) {
                float gg = Vf[i].x * Vf[k].x;
                gg = fmaf(Vf[i].y, Vf[k].y, gg);
                gg = fmaf(Vf[i].z, Vf[k].z, gg);
                gg = fmaf(Vf[i].w, Vf[k].w, gg);
#pragma unroll
                for (int m = 16; m >= 1; m >>= 1)
                    gg += __shfl_xor_sync(0xffffffffu, gg, m);
                if (lane == 0) gpart[w * 36 + idx] = gg;
                ++idx;
            }
        }
    }
    __syncthreads();
    if (t < 36) {
        float s = 0.f;
#pragma unroll
        for (int ww = 0; ww < 16; ++ww) s += gpart[ww * 36 + t];
        gpart[t] = s;
    }
    __syncthreads();
    if (t == 0) {
        float Gs[ORDER][ORDER];
        int id2 = 0;
        for (int i = 0; i < ORDER; ++i)
            for (int k = i; k < ORDER; ++k) {
                Gs[i][k] = gpart[id2]; Gs[k][i] = gpart[id2]; ++id2;
            }
        float rn[ORDER];
        for (int i = 0; i < ORDER; ++i) rn[i] = 1.0f / sqrtf(Gs[i][i]);
        float T[ORDER][ORDER];
        for (int i = 0; i < ORDER; ++i)
            for (int k = 0; k < ORDER; ++k) T[i][k] = 0.f;
        for (int i = 0; i < ORDER; ++i) T[i][i] = 2.f;
        for (int c = 1; c < ORDER; ++c)
            for (int r = 0; r < c; ++r) {
                float s = 0.f;
                for (int m = r; m < c; ++m)
                    s += T[r][m] * (Gs[m][c] * rn[m] * rn[c]);
                T[r][c] = -2.f * s;
            }
        for (int i = 0; i < ORDER; ++i)
            for (int k = 0; k < ORDER; ++k)
                Tneg[i * 8 + k] = -(rn[i] * T[i][k] * rn[k]);
    }

    // ---- packed V for pass C (persistent) ----
    ull V0[ORDER], V1[ORDER];
#pragma unroll
    for (int k = 0; k < ORDER; ++k) {
        V0[k] = pack2(Vf[k].x, Vf[k].y);
        V1[k] = pack2(Vf[k].z, Vf[k].w);
    }

    // ---- v fragments for MMA: hi/lo tf32 split, 16 chunks ----
    // A-frag row = g4 (v index), col = q / q+4 within the 8-col chunk.
    uint32_t vh0[16], vh2[16], vl0[16], vl2[16];
#pragma unroll
    for (int j = 0; j < 16; ++j) {
        const float f0 = v[g4 * NCOLS + cbase + 8 * j + q];
        const float f2 = v[g4 * NCOLS + cbase + 8 * j + q + 4];
        vh0[j] = cvt_tf32(f0);
        vl0[j] = cvt_tf32(f0 - __uint_as_float(vh0[j]));
        vh2[j] = cvt_tf32(f2);
        vl2[j] = cvt_tf32(f2 - __uint_as_float(vh2[j]));
    }

    const float4 dv = *reinterpret_cast<const float4*>(d + c0);
    const float4 bv = *reinterpret_cast<const float4*>(bias + c0);
    const ull d01 = pack2(dv.x, dv.y), d23 = pack2(dv.z, dv.w);
    const ull b01 = pack2(bv.x, bv.y), b23 = pack2(bv.z, bv.w);

    __syncthreads();   // Tneg visible

    float* yp = y + c0;
    const uint32_t zu = 0;

    // ================= Pipelined main loop =================
#pragma unroll 1
    for (int tt = 0; tt < NT; ++tt) {
        const int buf = tt & 1;

        cp_wait0();
        __syncthreads();               // tile tt visible; prev pass C done

        if (tt + 1 < NT) {
#pragma unroll
            for (int j = 0; j < TILE; ++j) {
                const int jr = (tt + 1) * TILE + j;
                const int rc = (jr < nr) ? jr : (nr - 1);
                cp16(xb_base + (uint32_t)(((1 - buf) * TILE + j) * SROW + c0) * 4,
                     x + (size_t)(r0 + rc) * NCOLS + c0);
            }
            cp_commit();
        }

        const float* xs = &xbuf[buf * TILE * SROW];

        // ---- pass A: tensor-core dots (no shuffles) ----
        // B-frag: b0 = x[row g4][col cbase+8j+q], b1 = same +4.
        {
            float c0f = 0.f, c1f = 0.f, c2f = 0.f, c3f = 0.f;
            const float* xg = xs + g4 * SROW + cbase + q;
#pragma unroll
            for (int j = 0; j < 16; ++j) {
                const float xb0 = xg[8 * j];
                const float xb1 = xg[8 * j + 4];
                const uint32_t xh0 = cvt_tf32(xb0);
                const uint32_t xh1 = cvt_tf32(xb1);
                const uint32_t xl0 = cvt_tf32(xb0 - __uint_as_float(xh0));
                const uint32_t xl1 = cvt_tf32(xb1 - __uint_as_float(xh1));
                mma_tf32(c0f, c1f, c2f, c3f, vh0[j], zu, vh2[j], zu, xh0, xh1);
                mma_tf32(c0f, c1f, c2f, c3f, vh0[j], zu, vh2[j], zu, xl0, xl1);
                mma_tf32(c0f, c1f, c2f, c3f, vl0[j], zu, vl2[j], zu, xh0, xh1);
            }
            // C-frag: c0,c1 = a[i=g4][rows 2q, 2q+1] over this warp's 128 cols
            *reinterpret_cast<float2*>(&asum[w * 66 + g4 * 8 + 2 * q]) =
                make_float2(c0f, c1f);
        }
        __syncthreads();

        // ---- pass B: collapse 16 warps + T' (64 threads, R2 pattern) ----
        if (t < 64) {
            const int row = t >> 3, s = t & 7;
            float a = 0.f;
#pragma unroll
            for (int ww = 0; ww < 16; ++ww)
                a += asum[ww * 66 + s * 8 + row];
            float bk = 0.f;
#pragma unroll
            for (int i = 0; i < 8; ++i) {
                const float ai = __shfl_sync(0xffffffffu, a, (lane & 24) | i);
                bk = fmaf(ai, Tneg[i * 8 + s], bk);
            }
            A2[(row * 8 + s) * 2]     = bk;
            A2[(row * 8 + s) * 2 + 1] = bk;
        }
        __syncthreads();

        // ---- pass C: correction + scale + store (x from padded smem) ----
#pragma unroll
        for (int j = 0; j < TILE; ++j) {
            const int jr = tt * TILE + j;
            if (jr < nr) {
                const float4 xv = *reinterpret_cast<const float4*>(xs + j * SROW + c0);
                ull a01 = pack2(xv.x, xv.y);
                ull a23 = pack2(xv.z, xv.w);
#pragma unroll
                for (int i = 0; i < 8; ++i) {
                    const ull bb = *reinterpret_cast<const ull*>(&A2[(j * 8 + i) * 2]);
                    a01 = ffma2(bb, V0[i], a01);   // Tneg carries the minus
                    a23 = ffma2(bb, V1[i], a23);
                }
                a01 = ffma2(a01, d01, b01);
                a23 = ffma2(a23, d23, b23);
                const float2 o0 = unpack2(a01), o1 = unpack2(a23);
                __stcs(reinterpret_cast<float4*>(yp + (size_t)(r0 + jr) * NCOLS),
                       make_float4(o0.x, o0.y, o1.x, o1.y));
            }
        }
    }
}

extern "C" void kernel_launch(void* const* d_in, const int* in_sizes, int n_in,
                              void* d_out, int out_size) {
    const float* x    = (const float*)d_in[0];
    const float* v    = (const float*)d_in[1];
    const float* dvec = (const float*)d_in[2];
    const float* bias = (const float*)d_in[3];
    float* y = (float*)d_out;
    (void)in_sizes; (void)n_in; (void)out_size;

    const int dyn = 2 * TILE * SROW * (int)sizeof(float);   // 131328 B
    static int attr_set = 0;
    if (!attr_set) {
        cudaFuncSetAttribute(orth_mma,
                             cudaFuncAttributeMaxDynamicSharedMemorySize, dyn);
        attr_set = 1;
    }
    orth_mma<<<NB, TPB, dyn>>>(x, v, dvec, bias, y);
}